// round 14
// baseline (speedup 1.0000x reference)
#include <cuda_runtime.h>
#include <cstdint>
#include <math.h>

#define Bn 8
#define Tn 2048
#define Cn 1024
#define Hn 64

// ---------------- device scratch (sanctioned no-alloc path) ----------------
__device__ float g_q[Bn * Tn * Hn];
__device__ float g_k[Bn * Tn * Hn];
__device__ float g_v[Bn * Tn * Hn];                 // V fp32 [b][t][h]
__device__ unsigned short g_vht[Bn * Hn * Tn];      // V bf16 hi, transposed [b][h][t]
__device__ unsigned short g_vlt[Bn * Hn * Tn];      // V bf16 lo, transposed
__device__ unsigned short g_wt_hi[3 * Hn * Cn];     // W bf16 hi, [o*64+n][k]
__device__ unsigned short g_wt_lo[3 * Hn * Cn];     // W bf16 lo
__device__ int g_ctr;                               // work-steal counter

__device__ __forceinline__ float tf32_round(float x) {
    uint32_t u;
    asm("cvt.rna.tf32.f32 %0, %1;" : "=r"(u) : "f"(x));
    return __uint_as_float(u);
}
__device__ __forceinline__ uint32_t bfpack(float hi, float lo) {
    uint32_t d;
    asm("cvt.rn.bf16x2.f32 %0, %1, %2;" : "=r"(d) : "f"(hi), "f"(lo));
    return d;
}
__device__ __forceinline__ uint32_t smem_u32(const void* p) {
    uint32_t a;
    asm("{ .reg .u64 t; cvta.to.shared.u64 t, %1; cvt.u32.u64 %0, t; }" : "=r"(a) : "l"(p));
    return a;
}
__device__ __forceinline__ void cp16(uint32_t s, const void* g) {
    asm volatile("cp.async.cg.shared.global [%0], [%1], 16;" :: "r"(s), "l"(g));
}
#define CP_COMMIT() asm volatile("cp.async.commit_group;" ::: "memory")
#define CP_WAIT1()  asm volatile("cp.async.wait_group 1;" ::: "memory")
#define CP_WAIT0()  asm volatile("cp.async.wait_group 0;" ::: "memory")

__device__ __forceinline__ void mma_tf32(float* c, const uint32_t* a, const uint32_t* b) {
    asm volatile(
        "mma.sync.aligned.m16n8k8.row.col.f32.tf32.tf32.f32 "
        "{%0,%1,%2,%3}, {%4,%5,%6,%7}, {%8,%9}, {%0,%1,%2,%3};"
        : "+f"(c[0]), "+f"(c[1]), "+f"(c[2]), "+f"(c[3])
        : "r"(a[0]), "r"(a[1]), "r"(a[2]), "r"(a[3]), "r"(b[0]), "r"(b[1]));
}
__device__ __forceinline__ void mma_bf16(float* c, const uint32_t* a, const uint32_t* b) {
    asm volatile(
        "mma.sync.aligned.m16n8k16.row.col.f32.bf16.bf16.f32 "
        "{%0,%1,%2,%3}, {%4,%5,%6,%7}, {%8,%9}, {%0,%1,%2,%3};"
        : "+f"(c[0]), "+f"(c[1]), "+f"(c[2]), "+f"(c[3])
        : "r"(a[0]), "r"(a[1]), "r"(a[2]), "r"(a[3]), "r"(b[0]), "r"(b[1]));
}

// ---------------------------------------------------------------------------
// prep: transpose weights to [o][n][k], bf16 Dekker split. (R8 verbatim)
// ---------------------------------------------------------------------------
__global__ void prep_w(const float* __restrict__ Wk, const float* __restrict__ Wq,
                       const float* __restrict__ Wv) {
    int idx = blockIdx.x * 256 + threadIdx.x;
    int o = idx / (Hn * Cn);
    int rem = idx - o * (Hn * Cn);
    int n = rem / Cn;
    int k = rem - n * Cn;
    const float* W = (o == 0) ? Wq : (o == 1) ? Wk : Wv;
    float v = W[k * Hn + n];
    uint32_t p = bfpack(v, v);
    float fb = __uint_as_float(p & 0xFFFF0000u);
    uint32_t pl = bfpack(v - fb, v - fb);
    g_wt_hi[idx] = (unsigned short)(p >> 16);
    g_wt_lo[idx] = (unsigned short)(pl >> 16);
}

__global__ void zero_ctr() { g_ctr = 0; }

// ---------------------------------------------------------------------------
// V transpose + bf16 split (R8 verbatim)
// ---------------------------------------------------------------------------
__global__ __launch_bounds__(128) void vt_split() {
    __shared__ float ts[64][65];
    const int b = blockIdx.y, t0 = blockIdx.x * 64;
    const int t = threadIdx.x;
    const float* vin = &g_v[((size_t)b * Tn + t0) * Hn];
    #pragma unroll
    for (int i = 0; i < 8; i++) {
        int c = t + i * 128;
        int r = c >> 4, c4 = (c & 15) * 4;
        float4 v = *(const float4*)&vin[r * Hn + c4];
        ts[r][c4] = v.x; ts[r][c4 + 1] = v.y; ts[r][c4 + 2] = v.z; ts[r][c4 + 3] = v.w;
    }
    __syncthreads();
    #pragma unroll
    for (int i = 0; i < 16; i++) {
        int c = t + i * 128;
        int h = c >> 5, c2 = (c & 31) * 2;
        float v0 = ts[c2][h], v1 = ts[c2 + 1][h];
        uint32_t ph = bfpack(v1, v0);
        float f0 = __uint_as_float(ph << 16);
        float f1 = __uint_as_float(ph & 0xFFFF0000u);
        uint32_t pl = bfpack(v1 - f1, v0 - f0);
        size_t o = (size_t)(b * Hn + h) * Tn + t0 + c2;
        *(uint32_t*)&g_vht[o] = ph;
        *(uint32_t*)&g_vlt[o] = pl;
    }
}

// ---------------------------------------------------------------------------
// QKV (R8 verbatim: 128-row CTA, 256 thr, bf16 k16 3-term, double-buffered)
// ---------------------------------------------------------------------------
#define QAST 40
#define QKV_STAGE_B 51200
#define QKV_SMEM (2 * QKV_STAGE_B)

__global__ __launch_bounds__(256) void qkv_mma(
    const float* __restrict__ x,
    const float* __restrict__ bk, const float* __restrict__ bq, const float* __restrict__ bv)
{
    extern __shared__ char smc[];
    const uint32_t sb = smem_u32(smc);
    const int t = threadIdx.x;
    const int wid = t >> 5, lane = t & 31;
    const int wm = wid >> 2, wn = wid & 3;
    const int g = lane >> 2, tg = lane & 3;
    const int m0 = blockIdx.x * 128;

    float c[4][6][4];
    #pragma unroll
    for (int mf = 0; mf < 4; mf++)
        #pragma unroll
        for (int nf = 0; nf < 6; nf++)
            #pragma unroll
            for (int r = 0; r < 4; r++) c[mf][nf][r] = 0.0f;

    auto issue = [&](int ch, int st) {
        const int k0 = ch * 32;
        uint32_t sA = sb + (uint32_t)st * QKV_STAGE_B;
        uint32_t sBh = sA + 20480;
        uint32_t sBl = sBh + 15360;
        #pragma unroll
        for (int i = 0; i < 4; i++) {
            int cc = t + i * 256;
            int r = cc >> 3, o = cc & 7;
            cp16(sA + r * 160 + o * 16, &x[(size_t)(m0 + r) * Cn + k0 + o * 4]);
        }
        #pragma unroll
        for (int i = 0; i < 3; i++) {
            int cc = t + i * 256;
            int r = cc >> 2, o = cc & 3;
            cp16(sBh + r * 80 + o * 16,
                 (const char*)g_wt_hi + ((size_t)r * Cn + k0 + o * 8) * 2);
            cp16(sBl + r * 80 + o * 16,
                 (const char*)g_wt_lo + ((size_t)r * Cn + k0 + o * 8) * 2);
        }
    };

    issue(0, 0);
    CP_COMMIT();

    for (int ch = 0; ch < 32; ch++) {
        if (ch < 31) { issue(ch + 1, (ch + 1) & 1); CP_COMMIT(); CP_WAIT1(); }
        else         { CP_WAIT0(); }
        __syncthreads();

        char* stg = smc + (ch & 1) * QKV_STAGE_B;
        const float* As = (const float*)stg;
        const uint32_t* Bhu = (const uint32_t*)(stg + 20480);
        const uint32_t* Blu = (const uint32_t*)(stg + 35840);

        #pragma unroll
        for (int ks = 0; ks < 2; ks++) {
            const int kk = ks * 16;
            uint32_t a_h[4][4], a_l[4][4], b_h[6][2], b_l[6][2];
            #pragma unroll
            for (int mf = 0; mf < 4; mf++) {
                int row = wm * 64 + mf * 16 + g;
                float2 p0 = *(const float2*)&As[row * QAST + kk + 2 * tg];
                float2 p1 = *(const float2*)&As[(row + 8) * QAST + kk + 2 * tg];
                float2 p2 = *(const float2*)&As[row * QAST + kk + 8 + 2 * tg];
                float2 p3 = *(const float2*)&As[(row + 8) * QAST + kk + 8 + 2 * tg];
                float2 ps[4] = {p0, p1, p2, p3};
                #pragma unroll
                for (int q = 0; q < 4; q++) {
                    uint32_t ph = bfpack(ps[q].y, ps[q].x);
                    a_h[mf][q] = ph;
                    float f0 = __uint_as_float(ph << 16);
                    float f1 = __uint_as_float(ph & 0xFFFF0000u);
                    a_l[mf][q] = bfpack(ps[q].y - f1, ps[q].x - f0);
                }
            }
            #pragma unroll
            for (int nf = 0; nf < 6; nf++) {
                int n = wn * 48 + nf * 8 + g;
                int ab = n * 20 + ks * 8 + tg;
                b_h[nf][0] = Bhu[ab];
                b_h[nf][1] = Bhu[ab + 4];
                b_l[nf][0] = Blu[ab];
                b_l[nf][1] = Blu[ab + 4];
            }
            #pragma unroll
            for (int nf = 0; nf < 6; nf++)
                #pragma unroll
                for (int mf = 0; mf < 4; mf++)
                    mma_bf16(c[mf][nf], a_h[mf], b_h[nf]);
            #pragma unroll
            for (int nf = 0; nf < 6; nf++)
                #pragma unroll
                for (int mf = 0; mf < 4; mf++)
                    mma_bf16(c[mf][nf], a_h[mf], b_l[nf]);
            #pragma unroll
            for (int nf = 0; nf < 6; nf++)
                #pragma unroll
                for (int mf = 0; mf < 4; mf++)
                    mma_bf16(c[mf][nf], a_l[mf], b_h[nf]);
        }
        __syncthreads();
    }

    #pragma unroll
    for (int nf = 0; nf < 6; nf++) {
        int col = wn * 48 + nf * 8 + tg * 2;
        int o = col >> 6;
        int h = col & 63;
        float* gout = (o == 0) ? g_q : (o == 1) ? g_k : g_v;
        const float* bias = (o == 0) ? bq : (o == 1) ? bk : bv;
        float2 bb = *(const float2*)&bias[h];
        #pragma unroll
        for (int mf = 0; mf < 4; mf++) {
            int r0 = m0 + wm * 64 + mf * 16 + g;
            *(float2*)&gout[(size_t)r0 * Hn + h] =
                make_float2(c[mf][nf][0] + bb.x, c[mf][nf][1] + bb.y);
            *(float2*)&gout[(size_t)(r0 + 8) * Hn + h] =
                make_float2(c[mf][nf][2] + bb.x, c[mf][nf][3] + bb.y);
        }
    }
}

// ---------------------------------------------------------------------------
// Flash attention: R8 inner loop (64-wide chunks, 128 thr, double-buffered),
// persistent work-stealing grid (296 CTAs, 2/SM), heavy-first tile order.
// Stage: K 64x68 f32 (17408) + VhT 64x36 u32 (9216) + VlT (9216) = 35840 B.
// x2 = 71680 B -> 2 CTAs/SM.
// ---------------------------------------------------------------------------
#define KST 68
#define ATT_STAGE_B 35840
#define ATTN_SMEM (2 * ATT_STAGE_B)
#define NTILES (32 * Bn)

__global__ __launch_bounds__(128, 2) void attn_mma(float* __restrict__ out)
{
    extern __shared__ char smc[];
    const uint32_t sb = smem_u32(smc);
    __shared__ int s_tile;

    const int t = threadIdx.x;
    const int w = t >> 5, lane = t & 31;
    const int g = lane >> 2, tg = lane & 3;
    const float scale = 0.03125f;     // 1024^-0.5

    for (;;) {
        if (t == 0) s_tile = atomicAdd(&g_ctr, 1);
        __syncthreads();
        const int n = s_tile;
        __syncthreads();          // s_tile consumed before next overwrite
        if (n >= NTILES) break;

        const int qi = 31 - (n >> 3);     // heavy tiles first (LPT)
        const int b = n & 7;
        const int q0 = qi * 64;
        const int rw = w * 16 + g;
        const long base = (long)b * Tn * Hn;

        auto issue = [&](int k0, int st) {
            uint32_t sK = sb + (uint32_t)st * ATT_STAGE_B;
            uint32_t sVh = sK + 17408;
            uint32_t sVl = sVh + 9216;
            #pragma unroll
            for (int i = 0; i < 8; i++) {
                int r = (t >> 4) + i * 8;
                int c4 = (t & 15) * 4;
                cp16(sK + (r * KST + c4) * 4, &g_k[base + (long)(k0 + r) * Hn + c4]);
            }
            #pragma unroll
            for (int i = 0; i < 4; i++) {
                int cc = t + i * 128;
                int h = cc >> 3, o = cc & 7;
                size_t go = ((size_t)(b * Hn + h) * Tn + k0 + o * 8) * 2;
                cp16(sVh + h * 144 + o * 16, (const char*)g_vht + go);
                cp16(sVl + h * 144 + o * 16, (const char*)g_vlt + go);
            }
        };

        issue(0, 0);
        CP_COMMIT();

        uint32_t qa[8][4];
        {
            const float* qp = &g_q[base + (long)(q0 + rw) * Hn];
            #pragma unroll
            for (int ksi = 0; ksi < 8; ksi++) {
                qa[ksi][0] = __float_as_uint(tf32_round(qp[ksi * 8 + tg] * scale));
                qa[ksi][1] = __float_as_uint(tf32_round(qp[8 * Hn + ksi * 8 + tg] * scale));
                qa[ksi][2] = __float_as_uint(tf32_round(qp[ksi * 8 + tg + 4] * scale));
                qa[ksi][3] = __float_as_uint(tf32_round(qp[8 * Hn + ksi * 8 + tg + 4] * scale));
            }
        }

        float m0 = -1e30f, m1 = -1e30f, l0 = 0.0f, l1 = 0.0f;
        float o[8][4];
        #pragma unroll
        for (int nf = 0; nf < 8; nf++)
            #pragma unroll
            for (int r = 0; r < 4; r++) o[nf][r] = 0.0f;

        for (int j = 0; j <= qi; j++) {
            if (j < qi) { issue((j + 1) * 64, (j + 1) & 1); CP_COMMIT(); CP_WAIT1(); }
            else        { CP_WAIT0(); }
            __syncthreads();

            char* stg = smc + (j & 1) * ATT_STAGE_B;
            const float* ksm = (const float*)stg;
            const uint32_t* vhu = (const uint32_t*)(stg + 17408);
            const uint32_t* vlu = (const uint32_t*)(stg + 26624);

            // ---- S = Qs . K^T ----
            float s[8][4];
            #pragma unroll
            for (int nf = 0; nf < 8; nf++)
                #pragma unroll
                for (int r = 0; r < 4; r++) s[nf][r] = 0.0f;

            #pragma unroll
            for (int ksi = 0; ksi < 8; ksi++) {
                uint32_t bf[8][2];
                #pragma unroll
                for (int nf = 0; nf < 8; nf++) {
                    int a = (nf * 8 + g) * KST + ksi * 8 + tg;
                    bf[nf][0] = __float_as_uint(ksm[a]);
                    bf[nf][1] = __float_as_uint(ksm[a + 4]);
                }
                #pragma unroll
                for (int nf = 0; nf < 8; nf++)
                    mma_tf32(s[nf], qa[ksi], bf[nf]);
            }

            if (j == qi) {
                #pragma unroll
                for (int nf = 0; nf < 8; nf++) {
                    int col = nf * 8 + 2 * tg;
                    if (col     > rw)     s[nf][0] = -1e30f;
                    if (col + 1 > rw)     s[nf][1] = -1e30f;
                    if (col     > rw + 8) s[nf][2] = -1e30f;
                    if (col + 1 > rw + 8) s[nf][3] = -1e30f;
                }
            }

            // ---- online softmax ----
            float mx0 = -1e30f, mx1 = -1e30f;
            #pragma unroll
            for (int nf = 0; nf < 8; nf++) {
                mx0 = fmaxf(mx0, fmaxf(s[nf][0], s[nf][1]));
                mx1 = fmaxf(mx1, fmaxf(s[nf][2], s[nf][3]));
            }
            #pragma unroll
            for (int off = 1; off <= 2; off <<= 1) {
                mx0 = fmaxf(mx0, __shfl_xor_sync(0xffffffffu, mx0, off));
                mx1 = fmaxf(mx1, __shfl_xor_sync(0xffffffffu, mx1, off));
            }
            float mn0 = fmaxf(m0, mx0), mn1 = fmaxf(m1, mx1);
            float rs0 = 0.0f, rs1 = 0.0f;
            #pragma unroll
            for (int nf = 0; nf < 8; nf++) {
                s[nf][0] = __expf(s[nf][0] - mn0);
                s[nf][1] = __expf(s[nf][1] - mn0);
                s[nf][2] = __expf(s[nf][2] - mn1);
                s[nf][3] = __expf(s[nf][3] - mn1);
                rs0 += s[nf][0] + s[nf][1];
                rs1 += s[nf][2] + s[nf][3];
            }
            #pragma unroll
            for (int off = 1; off <= 2; off <<= 1) {
                rs0 += __shfl_xor_sync(0xffffffffu, rs0, off);
                rs1 += __shfl_xor_sync(0xffffffffu, rs1, off);
            }
            float a0 = __expf(m0 - mn0), a1 = __expf(m1 - mn1);
            l0 = l0 * a0 + rs0; m0 = mn0;
            l1 = l1 * a1 + rs1; m1 = mn1;
            #pragma unroll
            for (int nf = 0; nf < 8; nf++) {
                o[nf][0] *= a0; o[nf][1] *= a0;
                o[nf][2] *= a1; o[nf][3] *= a1;
            }

            // ---- O += P . V (bf16 k16, 3 terms; thread-local A packing) ----
            #pragma unroll
            for (int ksi = 0; ksi < 4; ksi++) {
                uint32_t ah[4], al[4];
                #pragma unroll
                for (int q = 0; q < 4; q++) {
                    int sn = 2 * ksi + (q >> 1);
                    int e = (q & 1) * 2;
                    float s0 = s[sn][e], s1 = s[sn][e + 1];
                    uint32_t ph = bfpack(s1, s0);
                    ah[q] = ph;
                    float f0 = __uint_as_float(ph << 16);
                    float f1 = __uint_as_float(ph & 0xFFFF0000u);
                    al[q] = bfpack(s1 - f1, s0 - f0);
                }
                uint32_t bh[8][2], bl[8][2];
                #pragma unroll
                for (int nf = 0; nf < 8; nf++) {
                    int ab = (nf * 8 + g) * 36 + 8 * ksi + tg;
                    bh[nf][0] = vhu[ab];
                    bh[nf][1] = vhu[ab + 4];
                    bl[nf][0] = vlu[ab];
                    bl[nf][1] = vlu[ab + 4];
                }
                #pragma unroll
                for (int nf = 0; nf < 8; nf++)
                    mma_bf16(o[nf], ah, bh[nf]);
                #pragma unroll
                for (int nf = 0; nf < 8; nf++)
                    mma_bf16(o[nf], ah, bl[nf]);
                #pragma unroll
                for (int nf = 0; nf < 8; nf++)
                    mma_bf16(o[nf], al, bh[nf]);
            }
            __syncthreads();
        }

        float inv0 = 1.0f / l0, inv1 = 1.0f / l1;
        #pragma unroll
        for (int nf = 0; nf < 8; nf++) {
            int col = nf * 8 + 2 * tg;
            long r0 = base + (long)(q0 + rw) * Hn + col;
            *(float2*)&out[r0]          = make_float2(o[nf][0] * inv0, o[nf][1] * inv0);
            *(float2*)&out[r0 + 8 * Hn] = make_float2(o[nf][2] * inv1, o[nf][3] * inv1);
        }
    }
}

// ---------------------------------------------------------------------------
extern "C" void kernel_launch(void* const* d_in, const int* in_sizes, int n_in,
                              void* d_out, int out_size)
{
    const float* x  = (const float*)d_in[0];
    const float* Wk = (const float*)d_in[1];
    const float* bk = (const float*)d_in[2];
    const float* Wq = (const float*)d_in[3];
    const float* bq = (const float*)d_in[4];
    const float* Wv = (const float*)d_in[5];
    const float* bv = (const float*)d_in[6];
    float* out = (float*)d_out;

    prep_w<<<(3 * Hn * Cn) / 256, 256>>>(Wk, Wq, Wv);

    cudaFuncSetAttribute(qkv_mma, cudaFuncAttributeMaxDynamicSharedMemorySize, QKV_SMEM);
    qkv_mma<<<(Bn * Tn) / 128, 256, QKV_SMEM>>>(x, bk, bq, bv);

    vt_split<<<dim3(Tn / 64, Bn), 128>>>();
    zero_ctr<<<1, 1>>>();

    cudaFuncSetAttribute(attn_mma, cudaFuncAttributeMaxDynamicSharedMemorySize, ATTN_SMEM);
    attn_mma<<<296, 128, ATTN_SMEM>>>(out);
}

// round 16
// speedup vs baseline: 1.1741x; 1.1741x over previous
#include <cuda_runtime.h>
#include <cstdint>
#include <math.h>

#define Bn 8
#define Tn 2048
#define Cn 1024
#define Hn 64

// ---------------- device scratch (sanctioned no-alloc path) ----------------
__device__ float g_q[Bn * Tn * Hn];
__device__ float g_k[Bn * Tn * Hn];
__device__ float g_v[Bn * Tn * Hn];                 // V fp32 [b][t][h]
__device__ unsigned short g_vht[Bn * Hn * Tn];      // V bf16 hi, transposed [b][h][t]
__device__ unsigned short g_vlt[Bn * Hn * Tn];      // V bf16 lo, transposed
__device__ unsigned short g_wt_hi[3 * Hn * Cn];     // W bf16 hi, [o*64+n][k]
__device__ unsigned short g_wt_lo[3 * Hn * Cn];     // W bf16 lo

__device__ __forceinline__ float tf32_round(float x) {
    uint32_t u;
    asm("cvt.rna.tf32.f32 %0, %1;" : "=r"(u) : "f"(x));
    return __uint_as_float(u);
}
__device__ __forceinline__ uint32_t bfpack(float hi, float lo) {
    uint32_t d;
    asm("cvt.rn.bf16x2.f32 %0, %1, %2;" : "=r"(d) : "f"(hi), "f"(lo));
    return d;
}
__device__ __forceinline__ uint32_t smem_u32(const void* p) {
    uint32_t a;
    asm("{ .reg .u64 t; cvta.to.shared.u64 t, %1; cvt.u32.u64 %0, t; }" : "=r"(a) : "l"(p));
    return a;
}
__device__ __forceinline__ void cp16(uint32_t s, const void* g) {
    asm volatile("cp.async.cg.shared.global [%0], [%1], 16;" :: "r"(s), "l"(g));
}
#define CP_COMMIT() asm volatile("cp.async.commit_group;" ::: "memory")
#define CP_WAIT1()  asm volatile("cp.async.wait_group 1;" ::: "memory")
#define CP_WAIT0()  asm volatile("cp.async.wait_group 0;" ::: "memory")

__device__ __forceinline__ void mma_tf32(float* c, const uint32_t* a, const uint32_t* b) {
    asm volatile(
        "mma.sync.aligned.m16n8k8.row.col.f32.tf32.tf32.f32 "
        "{%0,%1,%2,%3}, {%4,%5,%6,%7}, {%8,%9}, {%0,%1,%2,%3};"
        : "+f"(c[0]), "+f"(c[1]), "+f"(c[2]), "+f"(c[3])
        : "r"(a[0]), "r"(a[1]), "r"(a[2]), "r"(a[3]), "r"(b[0]), "r"(b[1]));
}
__device__ __forceinline__ void mma_bf16(float* c, const uint32_t* a, const uint32_t* b) {
    asm volatile(
        "mma.sync.aligned.m16n8k16.row.col.f32.bf16.bf16.f32 "
        "{%0,%1,%2,%3}, {%4,%5,%6,%7}, {%8,%9}, {%0,%1,%2,%3};"
        : "+f"(c[0]), "+f"(c[1]), "+f"(c[2]), "+f"(c[3])
        : "r"(a[0]), "r"(a[1]), "r"(a[2]), "r"(a[3]), "r"(b[0]), "r"(b[1]));
}

// ---------------------------------------------------------------------------
// prep: transpose weights to [o][n][k], bf16 Dekker split. (R8 verbatim)
// ---------------------------------------------------------------------------
__global__ void prep_w(const float* __restrict__ Wk, const float* __restrict__ Wq,
                       const float* __restrict__ Wv) {
    int idx = blockIdx.x * 256 + threadIdx.x;
    int o = idx / (Hn * Cn);
    int rem = idx - o * (Hn * Cn);
    int n = rem / Cn;
    int k = rem - n * Cn;
    const float* W = (o == 0) ? Wq : (o == 1) ? Wk : Wv;
    float v = W[k * Hn + n];
    uint32_t p = bfpack(v, v);
    float fb = __uint_as_float(p & 0xFFFF0000u);
    uint32_t pl = bfpack(v - fb, v - fb);
    g_wt_hi[idx] = (unsigned short)(p >> 16);
    g_wt_lo[idx] = (unsigned short)(pl >> 16);
}

// ---------------------------------------------------------------------------
// V transpose + bf16 split (R8 verbatim)
// ---------------------------------------------------------------------------
__global__ __launch_bounds__(128) void vt_split() {
    __shared__ float ts[64][65];
    const int b = blockIdx.y, t0 = blockIdx.x * 64;
    const int t = threadIdx.x;
    const float* vin = &g_v[((size_t)b * Tn + t0) * Hn];
    #pragma unroll
    for (int i = 0; i < 8; i++) {
        int c = t + i * 128;
        int r = c >> 4, c4 = (c & 15) * 4;
        float4 v = *(const float4*)&vin[r * Hn + c4];
        ts[r][c4] = v.x; ts[r][c4 + 1] = v.y; ts[r][c4 + 2] = v.z; ts[r][c4 + 3] = v.w;
    }
    __syncthreads();
    #pragma unroll
    for (int i = 0; i < 16; i++) {
        int c = t + i * 128;
        int h = c >> 5, c2 = (c & 31) * 2;
        float v0 = ts[c2][h], v1 = ts[c2 + 1][h];
        uint32_t ph = bfpack(v1, v0);
        float f0 = __uint_as_float(ph << 16);
        float f1 = __uint_as_float(ph & 0xFFFF0000u);
        uint32_t pl = bfpack(v1 - f1, v0 - f0);
        size_t o = (size_t)(b * Hn + h) * Tn + t0 + c2;
        *(uint32_t*)&g_vht[o] = ph;
        *(uint32_t*)&g_vlt[o] = pl;
    }
}

// ---------------------------------------------------------------------------
// QKV (R8 verbatim: 128-row CTA, 256 thr, bf16 k16 3-term, double-buffered)
// ---------------------------------------------------------------------------
#define QAST 40
#define QKV_STAGE_B 51200
#define QKV_SMEM (2 * QKV_STAGE_B)

__global__ __launch_bounds__(256) void qkv_mma(
    const float* __restrict__ x,
    const float* __restrict__ bk, const float* __restrict__ bq, const float* __restrict__ bv)
{
    extern __shared__ char smc[];
    const uint32_t sb = smem_u32(smc);
    const int t = threadIdx.x;
    const int wid = t >> 5, lane = t & 31;
    const int wm = wid >> 2, wn = wid & 3;
    const int g = lane >> 2, tg = lane & 3;
    const int m0 = blockIdx.x * 128;

    float c[4][6][4];
    #pragma unroll
    for (int mf = 0; mf < 4; mf++)
        #pragma unroll
        for (int nf = 0; nf < 6; nf++)
            #pragma unroll
            for (int r = 0; r < 4; r++) c[mf][nf][r] = 0.0f;

    auto issue = [&](int ch, int st) {
        const int k0 = ch * 32;
        uint32_t sA = sb + (uint32_t)st * QKV_STAGE_B;
        uint32_t sBh = sA + 20480;
        uint32_t sBl = sBh + 15360;
        #pragma unroll
        for (int i = 0; i < 4; i++) {
            int cc = t + i * 256;
            int r = cc >> 3, o = cc & 7;
            cp16(sA + r * 160 + o * 16, &x[(size_t)(m0 + r) * Cn + k0 + o * 4]);
        }
        #pragma unroll
        for (int i = 0; i < 3; i++) {
            int cc = t + i * 256;
            int r = cc >> 2, o = cc & 3;
            cp16(sBh + r * 80 + o * 16,
                 (const char*)g_wt_hi + ((size_t)r * Cn + k0 + o * 8) * 2);
            cp16(sBl + r * 80 + o * 16,
                 (const char*)g_wt_lo + ((size_t)r * Cn + k0 + o * 8) * 2);
        }
    };

    issue(0, 0);
    CP_COMMIT();

    for (int ch = 0; ch < 32; ch++) {
        if (ch < 31) { issue(ch + 1, (ch + 1) & 1); CP_COMMIT(); CP_WAIT1(); }
        else         { CP_WAIT0(); }
        __syncthreads();

        char* stg = smc + (ch & 1) * QKV_STAGE_B;
        const float* As = (const float*)stg;
        const uint32_t* Bhu = (const uint32_t*)(stg + 20480);
        const uint32_t* Blu = (const uint32_t*)(stg + 35840);

        #pragma unroll
        for (int ks = 0; ks < 2; ks++) {
            const int kk = ks * 16;
            uint32_t a_h[4][4], a_l[4][4], b_h[6][2], b_l[6][2];
            #pragma unroll
            for (int mf = 0; mf < 4; mf++) {
                int row = wm * 64 + mf * 16 + g;
                float2 p0 = *(const float2*)&As[row * QAST + kk + 2 * tg];
                float2 p1 = *(const float2*)&As[(row + 8) * QAST + kk + 2 * tg];
                float2 p2 = *(const float2*)&As[row * QAST + kk + 8 + 2 * tg];
                float2 p3 = *(const float2*)&As[(row + 8) * QAST + kk + 8 + 2 * tg];
                float2 ps[4] = {p0, p1, p2, p3};
                #pragma unroll
                for (int q = 0; q < 4; q++) {
                    uint32_t ph = bfpack(ps[q].y, ps[q].x);
                    a_h[mf][q] = ph;
                    float f0 = __uint_as_float(ph << 16);
                    float f1 = __uint_as_float(ph & 0xFFFF0000u);
                    a_l[mf][q] = bfpack(ps[q].y - f1, ps[q].x - f0);
                }
            }
            #pragma unroll
            for (int nf = 0; nf < 6; nf++) {
                int n = wn * 48 + nf * 8 + g;
                int ab = n * 20 + ks * 8 + tg;
                b_h[nf][0] = Bhu[ab];
                b_h[nf][1] = Bhu[ab + 4];
                b_l[nf][0] = Blu[ab];
                b_l[nf][1] = Blu[ab + 4];
            }
            #pragma unroll
            for (int nf = 0; nf < 6; nf++)
                #pragma unroll
                for (int mf = 0; mf < 4; mf++)
                    mma_bf16(c[mf][nf], a_h[mf], b_h[nf]);
            #pragma unroll
            for (int nf = 0; nf < 6; nf++)
                #pragma unroll
                for (int mf = 0; mf < 4; mf++)
                    mma_bf16(c[mf][nf], a_h[mf], b_l[nf]);
            #pragma unroll
            for (int nf = 0; nf < 6; nf++)
                #pragma unroll
                for (int mf = 0; mf < 4; mf++)
                    mma_bf16(c[mf][nf], a_l[mf], b_h[nf]);
        }
        __syncthreads();
    }

    #pragma unroll
    for (int nf = 0; nf < 6; nf++) {
        int col = wn * 48 + nf * 8 + tg * 2;
        int o = col >> 6;
        int h = col & 63;
        float* gout = (o == 0) ? g_q : (o == 1) ? g_k : g_v;
        const float* bias = (o == 0) ? bq : (o == 1) ? bk : bv;
        float2 bb = *(const float2*)&bias[h];
        #pragma unroll
        for (int mf = 0; mf < 4; mf++) {
            int r0 = m0 + wm * 64 + mf * 16 + g;
            *(float2*)&gout[(size_t)r0 * Hn + h] =
                make_float2(c[mf][nf][0] + bb.x, c[mf][nf][1] + bb.y);
            *(float2*)&gout[(size_t)(r0 + 8) * Hn + h] =
                make_float2(c[mf][nf][2] + bb.x, c[mf][nf][3] + bb.y);
        }
    }
}

// ---------------------------------------------------------------------------
// Flash attention: R8 layout (128 thr, balanced pairs, 64-wide chunks) with
// SOFTWARE PIPELINING: 3 smem stages; iteration j interleaves PV(j) with
// S(j+1) for cross-phase MMA ILP. Stage 35840 B x3 = 107520 B, 1 CTA/SM.
// ---------------------------------------------------------------------------
#define KST 68
#define ATT_STAGE_B 35840
#define ATTN_SMEM (3 * ATT_STAGE_B)

__global__ __launch_bounds__(128) void attn_mma(float* __restrict__ out)
{
    extern __shared__ char smc[];
    const uint32_t sb = smem_u32(smc);

    const int t = threadIdx.x;
    const int w = t >> 5, lane = t & 31;
    const int g = lane >> 2, tg = lane & 3;
    const int b = blockIdx.y;
    const long base = (long)b * Tn * Hn;
    const float scale = 0.03125f;     // 1024^-0.5

    auto issue = [&](int k0, int st) {
        uint32_t sK = sb + (uint32_t)st * ATT_STAGE_B;
        uint32_t sVh = sK + 17408;
        uint32_t sVl = sVh + 9216;
        #pragma unroll
        for (int i = 0; i < 8; i++) {
            int r = (t >> 4) + i * 8;
            int c4 = (t & 15) * 4;
            cp16(sK + (r * KST + c4) * 4, &g_k[base + (long)(k0 + r) * Hn + c4]);
        }
        #pragma unroll
        for (int i = 0; i < 4; i++) {
            int cc = t + i * 128;
            int h = cc >> 3, o = cc & 7;
            size_t go = ((size_t)(b * Hn + h) * Tn + k0 + o * 8) * 2;
            cp16(sVh + h * 144 + o * 16, (const char*)g_vht + go);
            cp16(sVl + h * 144 + o * 16, (const char*)g_vlt + go);
        }
    };

    for (int tloop = 0; tloop < 2; tloop++) {
        const int qi = (tloop == 0) ? blockIdx.x : (31 - blockIdx.x);
        const int q0 = qi * 64;
        const int rw = w * 16 + g;

        // Q fragments
        uint32_t qa[8][4];
        {
            const float* qp = &g_q[base + (long)(q0 + rw) * Hn];
            #pragma unroll
            for (int ksi = 0; ksi < 8; ksi++) {
                qa[ksi][0] = __float_as_uint(tf32_round(qp[ksi * 8 + tg] * scale));
                qa[ksi][1] = __float_as_uint(tf32_round(qp[8 * Hn + ksi * 8 + tg] * scale));
                qa[ksi][2] = __float_as_uint(tf32_round(qp[ksi * 8 + tg + 4] * scale));
                qa[ksi][3] = __float_as_uint(tf32_round(qp[8 * Hn + ksi * 8 + tg + 4] * scale));
            }
        }

        // prologue: load stage 0 (+1), compute S(0)
        issue(0, 0);
        CP_COMMIT();
        if (qi >= 1) { issue(64, 1); CP_COMMIT(); CP_WAIT1(); }
        else         { CP_WAIT0(); }
        __syncthreads();

        float s_cur[8][4], s_next[8][4];
        {
            const float* ksm = (const float*)smc;   // stage 0
            #pragma unroll
            for (int nf = 0; nf < 8; nf++)
                #pragma unroll
                for (int r = 0; r < 4; r++) s_cur[nf][r] = 0.0f;
            #pragma unroll
            for (int ksi = 0; ksi < 8; ksi++) {
                uint32_t bf[8][2];
                #pragma unroll
                for (int nf = 0; nf < 8; nf++) {
                    int a = (nf * 8 + g) * KST + ksi * 8 + tg;
                    bf[nf][0] = __float_as_uint(ksm[a]);
                    bf[nf][1] = __float_as_uint(ksm[a + 4]);
                }
                #pragma unroll
                for (int nf = 0; nf < 8; nf++)
                    mma_tf32(s_cur[nf], qa[ksi], bf[nf]);
            }
        }

        float m0 = -1e30f, m1 = -1e30f, l0 = 0.0f, l1 = 0.0f;
        float o[8][4];
        #pragma unroll
        for (int nf = 0; nf < 8; nf++)
            #pragma unroll
            for (int r = 0; r < 4; r++) o[nf][r] = 0.0f;

        for (int j = 0; j <= qi; j++) {
            // stage (j+2)%3 is free (held chunk j-1, consumed last iter)
            __syncthreads();
            if (j + 2 <= qi) { issue((j + 2) * 64, (j + 2) % 3); CP_COMMIT(); CP_WAIT1(); }
            else             { CP_WAIT0(); }
            __syncthreads();

            char* stg = smc + (j % 3) * ATT_STAGE_B;
            const uint32_t* vhu = (const uint32_t*)(stg + 17408);
            const uint32_t* vlu = (const uint32_t*)(stg + 26624);
            const float* ksm2 = (const float*)(smc + ((j + 1) % 3) * ATT_STAGE_B);

            // ---- mask (diagonal chunk) on s_cur ----
            if (j == qi) {
                #pragma unroll
                for (int nf = 0; nf < 8; nf++) {
                    int col = nf * 8 + 2 * tg;
                    if (col     > rw)     s_cur[nf][0] = -1e30f;
                    if (col + 1 > rw)     s_cur[nf][1] = -1e30f;
                    if (col     > rw + 8) s_cur[nf][2] = -1e30f;
                    if (col + 1 > rw + 8) s_cur[nf][3] = -1e30f;
                }
            }

            // ---- online softmax on s_cur ----
            float mx0 = -1e30f, mx1 = -1e30f;
            #pragma unroll
            for (int nf = 0; nf < 8; nf++) {
                mx0 = fmaxf(mx0, fmaxf(s_cur[nf][0], s_cur[nf][1]));
                mx1 = fmaxf(mx1, fmaxf(s_cur[nf][2], s_cur[nf][3]));
            }
            #pragma unroll
            for (int off = 1; off <= 2; off <<= 1) {
                mx0 = fmaxf(mx0, __shfl_xor_sync(0xffffffffu, mx0, off));
                mx1 = fmaxf(mx1, __shfl_xor_sync(0xffffffffu, mx1, off));
            }
            float mn0 = fmaxf(m0, mx0), mn1 = fmaxf(m1, mx1);
            float rs0 = 0.0f, rs1 = 0.0f;
            #pragma unroll
            for (int nf = 0; nf < 8; nf++) {
                s_cur[nf][0] = __expf(s_cur[nf][0] - mn0);
                s_cur[nf][1] = __expf(s_cur[nf][1] - mn0);
                s_cur[nf][2] = __expf(s_cur[nf][2] - mn1);
                s_cur[nf][3] = __expf(s_cur[nf][3] - mn1);
                rs0 += s_cur[nf][0] + s_cur[nf][1];
                rs1 += s_cur[nf][2] + s_cur[nf][3];
            }
            #pragma unroll
            for (int off = 1; off <= 2; off <<= 1) {
                rs0 += __shfl_xor_sync(0xffffffffu, rs0, off);
                rs1 += __shfl_xor_sync(0xffffffffu, rs1, off);
            }
            float a0 = __expf(m0 - mn0), a1 = __expf(m1 - mn1);
            l0 = l0 * a0 + rs0; m0 = mn0;
            l1 = l1 * a1 + rs1; m1 = mn1;
            #pragma unroll
            for (int nf = 0; nf < 8; nf++) {
                o[nf][0] *= a0; o[nf][1] *= a0;
                o[nf][2] *= a1; o[nf][3] *= a1;
            }

            // ---- fused: PV(j) interleaved with S(j+1) ----
            const bool more = (j < qi);
            if (more) {
                #pragma unroll
                for (int nf = 0; nf < 8; nf++)
                    #pragma unroll
                    for (int r = 0; r < 4; r++) s_next[nf][r] = 0.0f;
            }
            #pragma unroll
            for (int ksi = 0; ksi < 4; ksi++) {
                // PV sub-block (s_cur, V stage j)
                uint32_t ah[4], al[4];
                #pragma unroll
                for (int q = 0; q < 4; q++) {
                    int sn = 2 * ksi + (q >> 1);
                    int e = (q & 1) * 2;
                    float s0 = s_cur[sn][e], s1 = s_cur[sn][e + 1];
                    uint32_t ph = bfpack(s1, s0);
                    ah[q] = ph;
                    float f0 = __uint_as_float(ph << 16);
                    float f1 = __uint_as_float(ph & 0xFFFF0000u);
                    al[q] = bfpack(s1 - f1, s0 - f0);
                }
                uint32_t bh[8][2], bl[8][2];
                #pragma unroll
                for (int nf = 0; nf < 8; nf++) {
                    int ab = (nf * 8 + g) * 36 + 8 * ksi + tg;
                    bh[nf][0] = vhu[ab];
                    bh[nf][1] = vhu[ab + 4];
                    bl[nf][0] = vlu[ab];
                    bl[nf][1] = vlu[ab + 4];
                }
                #pragma unroll
                for (int nf = 0; nf < 8; nf++)
                    mma_bf16(o[nf], ah, bh[nf]);
                #pragma unroll
                for (int nf = 0; nf < 8; nf++)
                    mma_bf16(o[nf], ah, bl[nf]);
                #pragma unroll
                for (int nf = 0; nf < 8; nf++)
                    mma_bf16(o[nf], al, bh[nf]);

                // S sub-block (qa, K stage j+1 -> s_next), 2 k-steps
                if (more) {
                    #pragma unroll
                    for (int h2 = 0; h2 < 2; h2++) {
                        const int ksj = 2 * ksi + h2;
                        uint32_t bf[8][2];
                        #pragma unroll
                        for (int nf = 0; nf < 8; nf++) {
                            int a = (nf * 8 + g) * KST + ksj * 8 + tg;
                            bf[nf][0] = __float_as_uint(ksm2[a]);
                            bf[nf][1] = __float_as_uint(ksm2[a + 4]);
                        }
                        #pragma unroll
                        for (int nf = 0; nf < 8; nf++)
                            mma_tf32(s_next[nf], qa[ksj], bf[nf]);
                    }
                }
            }
            if (more) {
                #pragma unroll
                for (int nf = 0; nf < 8; nf++)
                    #pragma unroll
                    for (int r = 0; r < 4; r++) s_cur[nf][r] = s_next[nf][r];
            }
        }

        float inv0 = 1.0f / l0, inv1 = 1.0f / l1;
        #pragma unroll
        for (int nf = 0; nf < 8; nf++) {
            int col = nf * 8 + 2 * tg;
            long r0 = base + (long)(q0 + rw) * Hn + col;
            *(float2*)&out[r0]          = make_float2(o[nf][0] * inv0, o[nf][1] * inv0);
            *(float2*)&out[r0 + 8 * Hn] = make_float2(o[nf][2] * inv1, o[nf][3] * inv1);
        }
        __syncthreads();
    }
}

// ---------------------------------------------------------------------------
extern "C" void kernel_launch(void* const* d_in, const int* in_sizes, int n_in,
                              void* d_out, int out_size)
{
    const float* x  = (const float*)d_in[0];
    const float* Wk = (const float*)d_in[1];
    const float* bk = (const float*)d_in[2];
    const float* Wq = (const float*)d_in[3];
    const float* bq = (const float*)d_in[4];
    const float* Wv = (const float*)d_in[5];
    const float* bv = (const float*)d_in[6];
    float* out = (float*)d_out;

    prep_w<<<(3 * Hn * Cn) / 256, 256>>>(Wk, Wq, Wv);

    cudaFuncSetAttribute(qkv_mma, cudaFuncAttributeMaxDynamicSharedMemorySize, QKV_SMEM);
    qkv_mma<<<(Bn * Tn) / 128, 256, QKV_SMEM>>>(x, bk, bq, bv);

    vt_split<<<dim3(Tn / 64, Bn), 128>>>();

    cudaFuncSetAttribute(attn_mma, cudaFuncAttributeMaxDynamicSharedMemorySize, ATTN_SMEM);
    attn_mma<<<dim3(16, Bn), 128, ATTN_SMEM>>>(out);
}